// round 7
// baseline (speedup 1.0000x reference)
#include <cuda_runtime.h>
#include <math.h>

#define TLEN    2048
#define HEADS_N 8
#define BATCH   2
#define SDIM    64
#define EDIM    512

// ---------------- scratch + resolved input pointers (device-resident) ----------
__device__ float g_q[BATCH*HEADS_N*TLEN*SDIM];
__device__ float g_k[BATCH*HEADS_N*TLEN*SDIM];
__device__ float g_v[BATCH*HEADS_N*TLEN*SDIM];
__device__ float g_vmean[BATCH*HEADS_N*SDIM];
__device__ float g_attn[BATCH*TLEN*EDIM];

__device__ const float*        g_pWq;
__device__ const float*        g_pWk;
__device__ const float*        g_pWv;
__device__ const unsigned int* g_pmask;

// ---------------- prologue: content-based identification of mask ---------------
__global__ void select_inputs(const float* c0, const float* c1,
                              const float* c2, const float* c3, int x_first) {
    __shared__ int bad[4];
    const float* cand[4] = {c0, c1, c2, c3};
    if (threadIdx.x < 4) bad[threadIdx.x] = 0;
    __syncthreads();
    for (int j = 0; j < 4; j++) {
        const unsigned int* p = (const unsigned int*)cand[j];
        int b = 0;
        for (int i = threadIdx.x; i < SDIM*SDIM; i += blockDim.x) {
            unsigned int v = p[i];
            if (v != 0u && v != 1u && v != 0x3F800000u) { b = 1; break; }
        }
        if (b) atomicOr(&bad[j], 1);
    }
    __syncthreads();
    if (threadIdx.x == 0) {
        int mi = -1;
        for (int j = 0; j < 4; j++) if (!bad[j]) { mi = j; break; }
        if (mi < 0) mi = x_first ? 0 : 3;
        const float* rest[3]; int n = 0;
        for (int j = 0; j < 4; j++) if (j != mi) rest[n++] = cand[j];
        g_pmask = (const unsigned int*)cand[mi];
        if (x_first) { g_pWq = rest[0]; g_pWk = rest[1]; g_pWv = rest[2]; }
        else         { g_pWk = rest[0]; g_pWq = rest[1]; g_pWv = rest[2]; }
    }
}

// ---------------- QKV projection (swizzled float4 smem) ----------------
// grid: (TLEN/128, H, B), 256 threads
__global__ void proj_kernel(const float* __restrict__ x) {
    extern __shared__ float sm[];
    float* sW = sm;              // 192 rows x 64, swizzled
    float* sX = sm + 192*64;     // 128 rows x 64, swizzled
    const int t0 = blockIdx.x * 128;
    const int h  = blockIdx.y;
    const int b  = blockIdx.z;
    const int tid = threadIdx.x;
    const float* W[3] = {g_pWq, g_pWk, g_pWv};

    // stage weights: row o (per matrix), swizzle mask = o&15
    for (int k = tid; k < 3*64*16; k += 256) {
        int row = k >> 4, i4 = k & 15;          // row in 0..191
        int mm = row >> 6, o = row & 63;
        float4 f = *(const float4*)&W[mm][o*SDIM + i4*4];
        *(float4*)&sW[row*64 + ((i4 ^ o) & 15)*4] = f;
    }
    for (int k = tid; k < 128*16; k += 256) {
        int row = k >> 4, i4 = k & 15;
        float4 f = *(const float4*)&x[(size_t)(b*TLEN + t0 + row)*EDIM + h*SDIM + i4*4];
        *(float4*)&sX[row*64 + ((i4 ^ (row & 15)) & 15)*4] = f;
    }
    __syncthreads();

    for (int idx = tid; idx < 128*192; idx += 256) {
        int row = idx / 192;                    // x row 0..127
        int rem = idx - row*192;                // 0..191 = weight row
        float a = 0.f;
        const int mw = rem & 15;                // weight swizzle mask (o&15)
        const int mx = row & 15;
        #pragma unroll
        for (int i4 = 0; i4 < 16; i4++) {
            float4 w4 = *(const float4*)&sW[rem*64 + ((i4 ^ mw) & 15)*4];
            float4 x4 = *(const float4*)&sX[row*64 + ((i4 ^ mx) & 15)*4];
            a = fmaf(w4.x, x4.x, a); a = fmaf(w4.y, x4.y, a);
            a = fmaf(w4.z, x4.z, a); a = fmaf(w4.w, x4.w, a);
        }
        int mm = rem >> 6, o = rem & 63;
        float* dst = (mm == 0) ? g_q : (mm == 1) ? g_k : g_v;
        dst[((size_t)(b*HEADS_N + h)*TLEN + t0 + row)*SDIM + o] = a;
    }
}

// ---------------- V mean (for masked query rows) ----------------
__global__ void vmean_kernel() {
    const int bh  = blockIdx.x;
    const int tid = threadIdx.x;
    const int d   = tid & 63;
    const int ch  = tid >> 6;
    __shared__ float red[4][64];
    float a = 0.f;
    for (int l = ch; l < TLEN; l += 4)
        a += g_v[((size_t)bh*TLEN + l)*SDIM + d];
    red[ch][d] = a;
    __syncthreads();
    if (ch == 0)
        g_vmean[bh*SDIM + d] =
            (red[0][d] + red[1][d] + red[2][d] + red[3][d]) * (1.f/(float)TLEN);
}

// ---------------- fused flash attention with relative position ----------------
// grid: (TLEN/64, H, B), 256 threads (16x16, 4x4 micro-tile)
// scores[i,c] = 512^-0.5 * q_i.k_c + q_i . Er[h, t-1-(i-c)]  for c <= i
// Output layout replicates reference transpose-reshape scramble:
//   O[b,t,h,s] -> pre-Wo row R = h*256 + (t>>3), col C = (t&7)*64 + s
__global__ void __launch_bounds__(256, 2) attn_kernel(const float* __restrict__ Er) {
    extern __shared__ float sm[];
    float* sQt = sm;               // [s][i]  64x64 swizzled
    float* sKt = sQt + 4096;       // [s][c]  64x64 swizzled (pre-scaled)
    float* sV  = sKt + 4096;       // [lc][d] 64x64 swizzled
    float* sPt = sV  + 4096;       // [lc][i] 64x64 swizzled
    float* sEr = sPt + 4096;       // [s][o]  64x128 swizzled (o: 0..126)

    const int i0 = blockIdx.x * 64;
    const int h  = blockIdx.y;
    const int b  = blockIdx.z;
    const int tid = threadIdx.x;
    const int tx = tid & 15;
    const int ty = tid >> 4;
    const float scale2 = 0.04419417382415922f;   // 512^-0.5

    const float* gq = g_q + (size_t)(b*HEADS_N + h)*TLEN*SDIM;
    const float* gk = g_k + (size_t)(b*HEADS_N + h)*TLEN*SDIM;
    const float* gv = g_v + (size_t)(b*HEADS_N + h)*TLEN*SDIM;

    // stage Q transposed+swizzled (once)
    for (int k = tid; k < 1024; k += 256) {
        int li = k >> 4, s4 = k & 15;
        float4 f = *(const float4*)&gq[(size_t)(i0 + li)*SDIM + s4*4];
        int base = s4*4*64 + (((li >> 2) ^ s4) & 15)*4 + (li & 3);
        sQt[base]       = f.x;
        sQt[base + 64]  = f.y;
        sQt[base + 128] = f.z;
        sQt[base + 192] = f.w;
    }

    float m[4], l[4], O[4][4];
    #pragma unroll
    for (int r = 0; r < 4; r++) {
        m[r] = -1e30f; l[r] = 0.f;
        #pragma unroll
        for (int c = 0; c < 4; c++) O[r][c] = 0.f;
    }

    const int nt = (i0 >> 6) + 1;
    const int e0l = 15 + tx - ty;      // logical col4 of re[0..3] (0..30)
    const int pc4 = ((ty ^ tx) & 15)*4;

    for (int ct = 0; ct < nt; ct++) {
        const int c0 = ct * 64;
        __syncthreads();   // prev iteration fully consumed (also covers Q staging)

        // stage K (transposed+swizzled, pre-scaled) and V (row-major swizzled)
        for (int k = tid; k < 1024; k += 256) {
            int li = k >> 4, s4 = k & 15;
            float4 f = *(const float4*)&gk[(size_t)(c0 + li)*SDIM + s4*4];
            int base = s4*4*64 + (((li >> 2) ^ s4) & 15)*4 + (li & 3);
            sKt[base]       = f.x * scale2;
            sKt[base + 64]  = f.y * scale2;
            sKt[base + 128] = f.z * scale2;
            sKt[base + 192] = f.w * scale2;
            float4 v = *(const float4*)&gv[(size_t)(c0 + li)*SDIM + s4*4];
            *(float4*)&sV[li*64 + ((s4 ^ (li >> 2)) & 15)*4] = v;
        }
        // stage Er rows jbase..jbase+126, transposed+swizzled
        const int jbase = TLEN - 64 - i0 + c0;     // >= 0
        for (int k = tid; k < 2032; k += 256) {
            int o = k >> 4, s4 = k & 15;
            int j = jbase + o;
            float4 f;
            if (j < TLEN) f = *(const float4*)&Er[((size_t)h*TLEN + j)*SDIM + s4*4];
            else          f = make_float4(0.f, 0.f, 0.f, 0.f);
            int c4s = ((o >> 2) & 16) | (((o >> 2) ^ s4) & 15);
            int base = s4*4*128 + c4s*4 + (o & 3);
            sEr[base]       = f.x;
            sEr[base + 128] = f.y;
            sEr[base + 256] = f.z;
            sEr[base + 384] = f.w;
        }
        __syncthreads();

        float acc[4][4];
        #pragma unroll
        for (int r = 0; r < 4; r++)
            #pragma unroll
            for (int c = 0; c < 4; c++) acc[r][c] = 0.f;

        #pragma unroll 4
        for (int s4 = 0; s4 < 16; s4++) {
            const int mq = ((ty ^ s4) & 15)*4;
            const int mk = ((tx ^ s4) & 15)*4;
            const int e0 = (((e0l & 16) | ((e0l ^ s4) & 15)))*4;
            const int e1l = e0l + 1;
            const int e1 = (((e1l & 16) | ((e1l ^ s4) & 15)))*4;
            #pragma unroll
            for (int j = 0; j < 4; j++) {
                const int s = s4*4 + j;
                float4 q4 = *(const float4*)&sQt[s*64 + mq];
                float4 k4 = *(const float4*)&sKt[s*64 + mk];
                float4 ea = *(const float4*)&sEr[s*128 + e0];
                float4 eb = *(const float4*)&sEr[s*128 + e1];
                float rq[4] = {q4.x, q4.y, q4.z, q4.w};
                float rk[4] = {k4.x, k4.y, k4.z, k4.w};
                float re[8] = {ea.x, ea.y, ea.z, ea.w, eb.x, eb.y, eb.z, eb.w};
                #pragma unroll
                for (int r = 0; r < 4; r++)
                    #pragma unroll
                    for (int c = 0; c < 4; c++)
                        acc[r][c] = fmaf(rq[r], rk[c] + re[3 + c - r], acc[r][c]);
            }
        }

        if (c0 == i0) {   // diagonal tile: causal mask
            #pragma unroll
            for (int r = 0; r < 4; r++)
                #pragma unroll
                for (int c = 0; c < 4; c++)
                    if (tx*4 + c > ty*4 + r) acc[r][c] = -1e30f;
        }

        // online softmax (rows owned by 16 lanes sharing ty)
        #pragma unroll
        for (int r = 0; r < 4; r++) {
            float rowmax = fmaxf(fmaxf(acc[r][0], acc[r][1]),
                                 fmaxf(acc[r][2], acc[r][3]));
            #pragma unroll
            for (int off = 8; off > 0; off >>= 1)
                rowmax = fmaxf(rowmax, __shfl_xor_sync(0xffffffffu, rowmax, off));
            float mnew = fmaxf(m[r], rowmax);
            float corr = __expf(m[r] - mnew);
            float ps = 0.f;
            #pragma unroll
            for (int c = 0; c < 4; c++) {
                float p = __expf(acc[r][c] - mnew);
                acc[r][c] = p;
                ps += p;
            }
            #pragma unroll
            for (int off = 8; off > 0; off >>= 1)
                ps += __shfl_xor_sync(0xffffffffu, ps, off);
            l[r] = l[r]*corr + ps;
            m[r] = mnew;
            #pragma unroll
            for (int c = 0; c < 4; c++) O[r][c] *= corr;
        }

        // stage P transposed+swizzled: row lc = tx*4+c, col i = ty*4+r
        #pragma unroll
        for (int c = 0; c < 4; c++)
            #pragma unroll
            for (int r = 0; r < 4; r++)
                sPt[(tx*4 + c)*64 + pc4 + r] = acc[r][c];
        __syncthreads();

        // O += P @ V
        #pragma unroll 4
        for (int l4 = 0; l4 < 16; l4++) {
            const int mp = ((ty ^ l4) & 15)*4;
            const int mv = ((tx ^ l4) & 15)*4;
            #pragma unroll
            for (int j = 0; j < 4; j++) {
                const int lc = l4*4 + j;
                float4 p4 = *(const float4*)&sPt[lc*64 + mp];
                float4 v4 = *(const float4*)&sV[lc*64 + mv];
                float rp[4] = {p4.x, p4.y, p4.z, p4.w};
                float rv[4] = {v4.x, v4.y, v4.z, v4.w};
                #pragma unroll
                for (int r = 0; r < 4; r++)
                    #pragma unroll
                    for (int c = 0; c < 4; c++)
                        O[r][c] = fmaf(rp[r], rv[c], O[r][c]);
            }
        }
    }

    // epilogue: scrambled layout R = h*256 + (i>>3), C = (i&7)*64 + d
    #pragma unroll
    for (int r = 0; r < 4; r++) {
        const int i  = i0 + ty*4 + r;
        const unsigned int mk = g_pmask[b*TLEN + i];
        const float inv = 1.f / l[r];
        const int R = h*256 + (i >> 3);
        const int Cbase = (i & 7) << 6;
        #pragma unroll
        for (int c = 0; c < 4; c++) {
            const int d = tx*4 + c;
            float val = (mk != 0u) ? O[r][c] * inv
                                   : g_vmean[(b*HEADS_N + h)*SDIM + d];
            g_attn[((size_t)(b*TLEN) + R)*EDIM + Cbase + d] = val;
        }
    }
}

// ---------------- output projection: out = attnS @ Wo^T + bo -------------------
__global__ void outproj_kernel(const float* __restrict__ Wo,
                               const float* __restrict__ bo,
                               float* __restrict__ out) {
    __shared__ float sAt[64*64];   // [s][m] swizzled
    __shared__ float sBt[64*64];   // [s][n] swizzled
    const int m0 = blockIdx.x * 64;
    const int n0 = blockIdx.y * 64;
    const int tid = threadIdx.x;
    const int tx = tid & 15;
    const int ty = tid >> 4;

    float acc[4][4];
    #pragma unroll
    for (int r = 0; r < 4; r++)
        #pragma unroll
        for (int c = 0; c < 4; c++) acc[r][c] = 0.f;

    for (int kc = 0; kc < EDIM; kc += 64) {
        __syncthreads();
        for (int k = tid; k < 1024; k += 256) {
            int rr = k >> 4, c4 = k & 15;
            float4 a = *(const float4*)&g_attn[(size_t)(m0 + rr)*EDIM + kc + c4*4];
            int basea = c4*4*64 + (((rr >> 2) ^ c4) & 15)*4 + (rr & 3);
            sAt[basea]       = a.x;
            sAt[basea + 64]  = a.y;
            sAt[basea + 128] = a.z;
            sAt[basea + 192] = a.w;
            float4 bw = *(const float4*)&Wo[(size_t)(n0 + rr)*EDIM + kc + c4*4];
            sBt[basea]       = bw.x;
            sBt[basea + 64]  = bw.y;
            sBt[basea + 128] = bw.z;
            sBt[basea + 192] = bw.w;
        }
        __syncthreads();
        #pragma unroll 4
        for (int s4 = 0; s4 < 16; s4++) {
            const int ma = ((ty ^ s4) & 15)*4;
            const int mb = ((tx ^ s4) & 15)*4;
            #pragma unroll
            for (int j = 0; j < 4; j++) {
                const int s = s4*4 + j;
                float4 a4 = *(const float4*)&sAt[s*64 + ma];
                float4 b4 = *(const float4*)&sBt[s*64 + mb];
                float ra[4] = {a4.x, a4.y, a4.z, a4.w};
                float rb[4] = {b4.x, b4.y, b4.z, b4.w};
                #pragma unroll
                for (int r = 0; r < 4; r++)
                    #pragma unroll
                    for (int c = 0; c < 4; c++)
                        acc[r][c] = fmaf(ra[r], rb[c], acc[r][c]);
            }
        }
    }

    #pragma unroll
    for (int r = 0; r < 4; r++)
        #pragma unroll
        for (int c = 0; c < 4; c++)
            out[(size_t)(m0 + ty*4 + r)*EDIM + n0 + tx*4 + c] =
                acc[r][c] + bo[n0 + tx*4 + c];
}

// ---------------- launch ----------------
extern "C" void kernel_launch(void* const* d_in, const int* in_sizes, int n_in,
                              void* d_out, int out_size) {
    int idx_x = -1, idx_Er = -1, idx_Wo = -1, idx_bo = -1;
    int cand[8]; int ncand = 0;
    for (int scale = 1; scale <= 4; scale *= 4) {
        idx_x = idx_Er = idx_Wo = idx_bo = -1; ncand = 0;
        for (int i = 0; i < n_in; i++) {
            long long s = in_sizes[i];
            if      (s == (long long)BATCH*TLEN*EDIM*scale)   idx_x  = i;
            else if (s == (long long)HEADS_N*TLEN*SDIM*scale) idx_Er = i;
            else if (s == (long long)EDIM*EDIM*scale)         idx_Wo = i;
            else if (s == (long long)EDIM*scale)              idx_bo = i;
            else if (s == (long long)SDIM*SDIM*scale && ncand < 8) cand[ncand++] = i;
        }
        if (idx_x >= 0 && idx_Er >= 0 && idx_Wo >= 0 && idx_bo >= 0 && ncand == 4)
            break;
    }
    if (!(idx_x >= 0 && idx_Er >= 0 && idx_Wo >= 0 && idx_bo >= 0 && ncand == 4)) {
        int wi = (n_in >= 9) ? 3 : 2;
        idx_x = 0; cand[0] = 1; cand[1] = wi; cand[2] = wi + 1; cand[3] = wi + 2;
        idx_Er = wi + 3; idx_Wo = wi + 4; idx_bo = wi + 5; ncand = 4;
    }

    const float* x  = (const float*)d_in[idx_x];
    const float* Er = (const float*)d_in[idx_Er];
    const float* Wo = (const float*)d_in[idx_Wo];
    const float* bo = (const float*)d_in[idx_bo];
    float* out = (float*)d_out;

    const int PROJ_SMEM = (192*64 + 128*64) * (int)sizeof(float);            // 81920 B
    const int ATTN_SMEM = (4*4096 + 64*128) * (int)sizeof(float);            // 98304 B
    cudaFuncSetAttribute(proj_kernel, cudaFuncAttributeMaxDynamicSharedMemorySize, PROJ_SMEM);
    cudaFuncSetAttribute(attn_kernel, cudaFuncAttributeMaxDynamicSharedMemorySize, ATTN_SMEM);

    select_inputs<<<1, 256>>>((const float*)d_in[cand[0]], (const float*)d_in[cand[1]],
                              (const float*)d_in[cand[2]], (const float*)d_in[cand[3]],
                              (idx_x == 0) ? 1 : 0);
    proj_kernel<<<dim3(TLEN/128, HEADS_N, BATCH), 256, PROJ_SMEM>>>(x);
    vmean_kernel<<<BATCH*HEADS_N, 256>>>();
    attn_kernel<<<dim3(TLEN/64, HEADS_N, BATCH), 256, ATTN_SMEM>>>(Er);
    outproj_kernel<<<dim3((BATCH*TLEN)/64, EDIM/64), 256>>>(Wo, bo, out);
}

// round 8
// speedup vs baseline: 1.0181x; 1.0181x over previous
#include <cuda_runtime.h>
#include <math.h>

#define TLEN    2048
#define HEADS_N 8
#define BATCH   2
#define SDIM    64
#define EDIM    512
#define QE_BH   2162688   // 4096 * 528 floats per (b,h)

// ---------------- scratch + resolved input pointers (device-resident) ----------
__device__ float g_q[BATCH*HEADS_N*TLEN*SDIM];
__device__ float g_k[BATCH*HEADS_N*TLEN*SDIM];
__device__ float g_v[BATCH*HEADS_N*TLEN*SDIM];
__device__ float g_vmean[BATCH*HEADS_N*SDIM];
__device__ float g_attn[BATCH*TLEN*EDIM];
__device__ float g_qe[BATCH*HEADS_N*QE_BH];   // triangular-packed QE bands

__device__ const float*        g_pWq;
__device__ const float*        g_pWk;
__device__ const float*        g_pWv;
__device__ const unsigned int* g_pmask;

// ---------------- tf32 helpers ----------------
__device__ __forceinline__ unsigned int f2tf32(float x) {
    unsigned int r;
    asm("cvt.rna.tf32.f32 %0, %1;" : "=r"(r) : "f"(x));
    return r;
}
__device__ __forceinline__ void mma_tf32(float d[4],
        unsigned int a0, unsigned int a1, unsigned int a2, unsigned int a3,
        unsigned int b0, unsigned int b1) {
    asm("mma.sync.aligned.m16n8k8.row.col.f32.tf32.tf32.f32 "
        "{%0,%1,%2,%3}, {%4,%5,%6,%7}, {%8,%9}, {%0,%1,%2,%3};"
        : "+f"(d[0]), "+f"(d[1]), "+f"(d[2]), "+f"(d[3])
        : "r"(a0), "r"(a1), "r"(a2), "r"(a3), "r"(b0), "r"(b1));
}

// ---------------- prologue: content-based identification of mask ---------------
__global__ void select_inputs(const float* c0, const float* c1,
                              const float* c2, const float* c3, int x_first) {
    __shared__ int bad[4];
    const float* cand[4] = {c0, c1, c2, c3};
    if (threadIdx.x < 4) bad[threadIdx.x] = 0;
    __syncthreads();
    for (int j = 0; j < 4; j++) {
        const unsigned int* p = (const unsigned int*)cand[j];
        int b = 0;
        for (int i = threadIdx.x; i < SDIM*SDIM; i += blockDim.x) {
            unsigned int v = p[i];
            if (v != 0u && v != 1u && v != 0x3F800000u) { b = 1; break; }
        }
        if (b) atomicOr(&bad[j], 1);
    }
    __syncthreads();
    if (threadIdx.x == 0) {
        int mi = -1;
        for (int j = 0; j < 4; j++) if (!bad[j]) { mi = j; break; }
        if (mi < 0) mi = x_first ? 0 : 3;
        const float* rest[3]; int n = 0;
        for (int j = 0; j < 4; j++) if (j != mi) rest[n++] = cand[j];
        g_pmask = (const unsigned int*)cand[mi];
        if (x_first) { g_pWq = rest[0]; g_pWk = rest[1]; g_pWv = rest[2]; }
        else         { g_pWk = rest[0]; g_pWq = rest[1]; g_pWv = rest[2]; }
    }
}

// ---------------- QKV projection (swizzled float4 smem) ----------------
__global__ void proj_kernel(const float* __restrict__ x) {
    extern __shared__ float sm[];
    float* sW = sm;              // 192 rows x 64, swizzled
    float* sX = sm + 192*64;     // 128 rows x 64, swizzled
    const int t0 = blockIdx.x * 128;
    const int h  = blockIdx.y;
    const int b  = blockIdx.z;
    const int tid = threadIdx.x;
    const float* W[3] = {g_pWq, g_pWk, g_pWv};

    for (int k = tid; k < 3*64*16; k += 256) {
        int row = k >> 4, i4 = k & 15;
        int mm = row >> 6, o = row & 63;
        float4 f = *(const float4*)&W[mm][o*SDIM + i4*4];
        *(float4*)&sW[row*64 + ((i4 ^ o) & 15)*4] = f;
    }
    for (int k = tid; k < 128*16; k += 256) {
        int row = k >> 4, i4 = k & 15;
        float4 f = *(const float4*)&x[(size_t)(b*TLEN + t0 + row)*EDIM + h*SDIM + i4*4];
        *(float4*)&sX[row*64 + ((i4 ^ (row & 15)) & 15)*4] = f;
    }
    __syncthreads();

    for (int idx = tid; idx < 128*192; idx += 256) {
        int row = idx / 192;
        int rem = idx - row*192;
        float a = 0.f;
        const int mw = rem & 15;
        const int mx = row & 15;
        #pragma unroll
        for (int i4 = 0; i4 < 16; i4++) {
            float4 w4 = *(const float4*)&sW[rem*64 + ((i4 ^ mw) & 15)*4];
            float4 x4 = *(const float4*)&sX[row*64 + ((i4 ^ mx) & 15)*4];
            a = fmaf(w4.x, x4.x, a); a = fmaf(w4.y, x4.y, a);
            a = fmaf(w4.z, x4.z, a); a = fmaf(w4.w, x4.w, a);
        }
        int mm = rem >> 6, o = rem & 63;
        float* dst = (mm == 0) ? g_q : (mm == 1) ? g_k : g_v;
        dst[((size_t)(b*HEADS_N + h)*TLEN + t0 + row)*SDIM + o] = a;
    }
}

// ---------------- rel-pos GEMM: QE[i_l][o] = q_{i0+i_l} . Er[h][T-64-i0+o] ------
// 3xtf32 mma.sync (hi*hi + hi*lo + lo*hi) for fp32-grade accuracy.
// grid: (528, H, B) — x triangular-decodes to (it, ochunk), ochunk in [0, it].
__global__ void __launch_bounds__(256) relgemm_kernel(const float* __restrict__ Er) {
    extern __shared__ float sm[];
    float* Qh = sm;              // [m=64][k] stride 68
    float* Ql = Qh + 64*68;
    float* Eh = Ql + 64*68;      // [k=64][n=o] stride 68
    float* El = Eh + 64*68;

    const int x = blockIdx.x;
    const int h = blockIdx.y, b = blockIdx.z;
    int it = (int)((sqrtf(8.f*(float)x + 1.f) - 1.f) * 0.5f);
    while ((it + 1)*(it + 2)/2 <= x) it++;
    while (it*(it + 1)/2 > x) it--;
    const int oc = x - it*(it + 1)/2;          // 0..it
    const int i0 = it * 64;
    const int j0 = TLEN - 64 - i0 + oc*64;     // Er row base (>= 0)

    const int tid = threadIdx.x;
    const float* gq = g_q + (size_t)(b*HEADS_N + h)*TLEN*SDIM + (size_t)i0*SDIM;
    const float* ge = Er + (size_t)h*TLEN*SDIM;

    // stage Q hi/lo [m][k]
    #pragma unroll
    for (int kk = 0; kk < 4; kk++) {
        int k = kk*256 + tid;
        int m = k >> 4, s4 = (k & 15)*4;
        float4 f = *(const float4*)&gq[m*SDIM + s4];
        float hx = __uint_as_float(f2tf32(f.x));
        float hy = __uint_as_float(f2tf32(f.y));
        float hz = __uint_as_float(f2tf32(f.z));
        float hw = __uint_as_float(f2tf32(f.w));
        *(float4*)&Qh[m*68 + s4] = make_float4(hx, hy, hz, hw);
        *(float4*)&Ql[m*68 + s4] = make_float4(
            __uint_as_float(f2tf32(f.x - hx)), __uint_as_float(f2tf32(f.y - hy)),
            __uint_as_float(f2tf32(f.z - hz)), __uint_as_float(f2tf32(f.w - hw)));
    }
    // stage Er transposed hi/lo: Eh[s][o] = Er[j0+o][s]
    #pragma unroll
    for (int kk = 0; kk < 4; kk++) {
        int k = kk*256 + tid;
        int s4 = (k >> 6)*4, o = k & 63;
        float4 f = *(const float4*)&ge[(size_t)(j0 + o)*SDIM + s4];
        float hv[4], lv[4];
        float fv[4] = {f.x, f.y, f.z, f.w};
        #pragma unroll
        for (int i = 0; i < 4; i++) {
            hv[i] = __uint_as_float(f2tf32(fv[i]));
            lv[i] = __uint_as_float(f2tf32(fv[i] - hv[i]));
        }
        #pragma unroll
        for (int i = 0; i < 4; i++) {
            Eh[(s4 + i)*68 + o] = hv[i];
            El[(s4 + i)*68 + o] = lv[i];
        }
    }
    __syncthreads();

    const int w = tid >> 5, lane = tid & 31;
    const int g = lane >> 2, tg = lane & 3;
    const int mr = (w & 3)*16 + g;     // rows mr, mr+8
    const int nb = (w >> 2)*32;        // col half

    float d[4][4];
    #pragma unroll
    for (int nt = 0; nt < 4; nt++)
        #pragma unroll
        for (int i = 0; i < 4; i++) d[nt][i] = 0.f;

    #pragma unroll
    for (int kk = 0; kk < 8; kk++) {
        const int k0 = kk*8;
        unsigned int ah0 = __float_as_uint(Qh[mr*68 + k0 + tg]);
        unsigned int ah1 = __float_as_uint(Qh[(mr + 8)*68 + k0 + tg]);
        unsigned int ah2 = __float_as_uint(Qh[mr*68 + k0 + tg + 4]);
        unsigned int ah3 = __float_as_uint(Qh[(mr + 8)*68 + k0 + tg + 4]);
        unsigned int al0 = __float_as_uint(Ql[mr*68 + k0 + tg]);
        unsigned int al1 = __float_as_uint(Ql[(mr + 8)*68 + k0 + tg]);
        unsigned int al2 = __float_as_uint(Ql[mr*68 + k0 + tg + 4]);
        unsigned int al3 = __float_as_uint(Ql[(mr + 8)*68 + k0 + tg + 4]);
        #pragma unroll
        for (int nt = 0; nt < 4; nt++) {
            const int n = nb + nt*8 + g;
            unsigned int bh0 = __float_as_uint(Eh[(k0 + tg)*68 + n]);
            unsigned int bh1 = __float_as_uint(Eh[(k0 + tg + 4)*68 + n]);
            unsigned int bl0 = __float_as_uint(El[(k0 + tg)*68 + n]);
            unsigned int bl1 = __float_as_uint(El[(k0 + tg + 4)*68 + n]);
            mma_tf32(d[nt], ah0, ah1, ah2, ah3, bh0, bh1);
            mma_tf32(d[nt], ah0, ah1, ah2, ah3, bl0, bl1);
            mma_tf32(d[nt], al0, al1, al2, al3, bh0, bh1);
        }
    }

    const int W = 64*(it + 1);
    float* qb = g_qe + (size_t)(b*HEADS_N + h)*QE_BH + (size_t)4096*(it*(it + 1)/2);
    const int colb = oc*64 + nb;
    #pragma unroll
    for (int nt = 0; nt < 4; nt++) {
        const int col = colb + nt*8 + 2*tg;
        *(float2*)&qb[(size_t)mr*W + col]       = make_float2(d[nt][0], d[nt][1]);
        *(float2*)&qb[(size_t)(mr + 8)*W + col] = make_float2(d[nt][2], d[nt][3]);
    }
}

// ---------------- V mean (for masked query rows) ----------------
__global__ void vmean_kernel() {
    const int bh  = blockIdx.x;
    const int tid = threadIdx.x;
    const int d   = tid & 63;
    const int ch  = tid >> 6;
    __shared__ float red[4][64];
    float a = 0.f;
    for (int l = ch; l < TLEN; l += 4)
        a += g_v[((size_t)bh*TLEN + l)*SDIM + d];
    red[ch][d] = a;
    __syncthreads();
    if (ch == 0)
        g_vmean[bh*SDIM + d] =
            (red[0][d] + red[1][d] + red[2][d] + red[3][d]) * (1.f/(float)TLEN);
}

// ---------------- fused flash attention (QK + precomputed QE + PV) -------------
// grid: (TLEN/64, H, B), 256 threads (16x16, 4x4 micro-tile)
// Output layout replicates reference transpose-reshape scramble:
//   O[b,t,h,s] -> pre-Wo row R = h*256 + (t>>3), col C = (t&7)*64 + s
__global__ void __launch_bounds__(256, 3) attn_kernel() {
    extern __shared__ float sm[];
    float* sQt = sm;               // [s][i]  64x64 swizzled
    float* sKt = sQt + 4096;       // [s][c]  64x64 swizzled (pre-scaled)
    float* sV  = sKt + 4096;       // [lc][d] 64x64 swizzled
    float* sPt = sV  + 4096;       // [lc][i] 64x64 swizzled

    const int i0 = blockIdx.x * 64;
    const int h  = blockIdx.y;
    const int b  = blockIdx.z;
    const int tid = threadIdx.x;
    const int tx = tid & 15;
    const int ty = tid >> 4;
    const float scale2 = 0.04419417382415922f;   // 512^-0.5

    const float* gq = g_q + (size_t)(b*HEADS_N + h)*TLEN*SDIM;
    const float* gk = g_k + (size_t)(b*HEADS_N + h)*TLEN*SDIM;
    const float* gv = g_v + (size_t)(b*HEADS_N + h)*TLEN*SDIM;

    const int it = i0 >> 6;
    const int Wqe = 64*(it + 1);
    const float* qeb = g_qe + (size_t)(b*HEADS_N + h)*QE_BH
                     + (size_t)4096*(it*(it + 1)/2);
    const int omax = i0 + 63;

    // stage Q transposed+swizzled (once)
    for (int k = tid; k < 1024; k += 256) {
        int li = k >> 4, s4 = k & 15;
        float4 f = *(const float4*)&gq[(size_t)(i0 + li)*SDIM + s4*4];
        int base = s4*4*64 + (((li >> 2) ^ s4) & 15)*4 + (li & 3);
        sQt[base]       = f.x;
        sQt[base + 64]  = f.y;
        sQt[base + 128] = f.z;
        sQt[base + 192] = f.w;
    }

    float m[4], l[4], O[4][4];
    #pragma unroll
    for (int r = 0; r < 4; r++) {
        m[r] = -1e30f; l[r] = 0.f;
        #pragma unroll
        for (int c = 0; c < 4; c++) O[r][c] = 0.f;
    }

    const int nt = it + 1;
    const int pc4 = ((ty ^ tx) & 15)*4;

    for (int ct = 0; ct < nt; ct++) {
        const int c0 = ct * 64;
        __syncthreads();   // prev iteration fully consumed (covers Q staging too)

        for (int k = tid; k < 1024; k += 256) {
            int li = k >> 4, s4 = k & 15;
            float4 f = *(const float4*)&gk[(size_t)(c0 + li)*SDIM + s4*4];
            int base = s4*4*64 + (((li >> 2) ^ s4) & 15)*4 + (li & 3);
            sKt[base]       = f.x * scale2;
            sKt[base + 64]  = f.y * scale2;
            sKt[base + 128] = f.z * scale2;
            sKt[base + 192] = f.w * scale2;
            float4 v = *(const float4*)&gv[(size_t)(c0 + li)*SDIM + s4*4];
            *(float4*)&sV[li*64 + ((s4 ^ (li >> 2)) & 15)*4] = v;
        }
        __syncthreads();

        float acc[4][4];
        #pragma unroll
        for (int r = 0; r < 4; r++)
            #pragma unroll
            for (int c = 0; c < 4; c++) acc[r][c] = 0.f;

        #pragma unroll 4
        for (int s4 = 0; s4 < 16; s4++) {
            const int mq = ((ty ^ s4) & 15)*4;
            const int mk = ((tx ^ s4) & 15)*4;
            #pragma unroll
            for (int j = 0; j < 4; j++) {
                const int s = s4*4 + j;
                float4 q4 = *(const float4*)&sQt[s*64 + mq];
                float4 k4 = *(const float4*)&sKt[s*64 + mk];
                float rq[4] = {q4.x, q4.y, q4.z, q4.w};
                float rk[4] = {k4.x, k4.y, k4.z, k4.w};
                #pragma unroll
                for (int r = 0; r < 4; r++)
                    #pragma unroll
                    for (int c = 0; c < 4; c++)
                        acc[r][c] = fmaf(rq[r], rk[c], acc[r][c]);
            }
        }

        // add precomputed rel-pos band: acc[r][c] += QE[i_l][63 - i_l + c_g]
        #pragma unroll
        for (int r = 0; r < 4; r++) {
            const int il = ty*4 + r;
            const int ob = 63 - il + c0 + tx*4;
            const float* rowp = qeb + (size_t)il*Wqe + ob;
            #pragma unroll
            for (int c = 0; c < 4; c++) {
                if (ob + c <= omax) acc[r][c] += __ldg(rowp + c);
            }
        }

        if (c0 == i0) {   // diagonal tile: causal mask
            #pragma unroll
            for (int r = 0; r < 4; r++)
                #pragma unroll
                for (int c = 0; c < 4; c++)
                    if (tx*4 + c > ty*4 + r) acc[r][c] = -1e30f;
        }

        // online softmax (rows owned by 16 lanes sharing ty)
        #pragma unroll
        for (int r = 0; r < 4; r++) {
            float rowmax = fmaxf(fmaxf(acc[r][0], acc[r][1]),
                                 fmaxf(acc[r][2], acc[r][3]));
            #pragma unroll
            for (int off = 8; off > 0; off >>= 1)
                rowmax = fmaxf(rowmax, __shfl_xor_sync(0xffffffffu, rowmax, off));
            float mnew = fmaxf(m[r], rowmax);
            float corr = __expf(m[r] - mnew);
            float ps = 0.f;
            #pragma unroll
            for (int c = 0; c < 4; c++) {
                float p = __expf(acc[r][c] - mnew);
                acc[r][c] = p;
                ps += p;
            }
            #pragma unroll
            for (int off = 8; off > 0; off >>= 1)
                ps += __shfl_xor_sync(0xffffffffu, ps, off);
            l[r] = l[r]*corr + ps;
            m[r] = mnew;
            #pragma unroll
            for (int c = 0; c < 4; c++) O[r][c] *= corr;
        }

        // stage P transposed+swizzled
        #pragma unroll
        for (int c = 0; c < 4; c++)
            #pragma unroll
            for (int r = 0; r < 4; r++)
                sPt[(tx*4 + c)*64 + pc4 + r] = acc[r][c];
        __syncthreads();

        // O += P @ V
        #pragma unroll 4
        for (int l4 = 0; l4 < 16; l4++) {
            const int mp = ((ty ^ l4) & 15)*4;
            const int mv = ((tx ^ l4) & 15)*4;
            #pragma unroll
            for (int j = 0; j < 4; j++) {
                const int lc = l4*4 + j;
                float4 p4 = *(const float4*)&sPt[lc*64 + mp];
                float4 v4 = *(const float4*)&sV[lc*64 + mv];
                float rp[4] = {p4.x, p4.y, p4.z, p4.w};
                float rv[4] = {v4.x, v4.y, v4.z, v4.w};
                #pragma unroll
                for (int r = 0; r < 4; r++)
                    #pragma unroll
                    for (int c = 0; c < 4; c++)
                        O[r][c] = fmaf(rp[r], rv[c], O[r][c]);
            }
        }
    }

    // epilogue: scrambled layout R = h*256 + (i>>3), C = (i&7)*64 + d
    #pragma unroll
    for (int r = 0; r < 4; r++) {
        const int i  = i0 + ty*4 + r;
        const unsigned int mk = g_pmask[b*TLEN + i];
        const float inv = 1.f / l[r];
        const int R = h*256 + (i >> 3);
        const int Cbase = (i & 7) << 6;
        #pragma unroll
        for (int c = 0; c < 4; c++) {
            const int d = tx*4 + c;
            float val = (mk != 0u) ? O[r][c] * inv
                                   : g_vmean[(b*HEADS_N + h)*SDIM + d];
            g_attn[((size_t)(b*TLEN) + R)*EDIM + Cbase + d] = val;
        }
    }
}

// ---------------- output projection: out = attnS @ Wo^T + bo -------------------
__global__ void outproj_kernel(const float* __restrict__ Wo,
                               const float* __restrict__ bo,
                               float* __restrict__ out) {
    __shared__ float sAt[64*64];
    __shared__ float sBt[64*64];
    const int m0 = blockIdx.x * 64;
    const int n0 = blockIdx.y * 64;
    const int tid = threadIdx.x;
    const int tx = tid & 15;
    const int ty = tid >> 4;

    float acc[4][4];
    #pragma unroll
    for (int r = 0; r < 4; r++)
        #pragma unroll
        for (int c = 0; c < 4; c++) acc[r][c] = 0.f;

    for (int kc = 0; kc < EDIM; kc += 64) {
        __syncthreads();
        for (int k = tid; k < 1024; k += 256) {
            int rr = k >> 4, c4 = k & 15;
            float4 a = *(const float4*)&g_attn[(size_t)(m0 + rr)*EDIM + kc + c4*4];
            int basea = c4*4*64 + (((rr >> 2) ^ c4) & 15)*4 + (rr & 3);
            sAt[basea]       = a.x;
            sAt[basea + 64]  = a.y;
            sAt[basea + 128] = a.z;
            sAt[basea + 192] = a.w;
            float4 bw = *(const float4*)&Wo[(size_t)(n0 + rr)*EDIM + kc + c4*4];
            sBt[basea]       = bw.x;
            sBt[basea + 64]  = bw.y;
            sBt[basea + 128] = bw.z;
            sBt[basea + 192] = bw.w;
        }
        __syncthreads();
        #pragma unroll 4
        for (int s4 = 0; s4 < 16; s4++) {
            const int ma = ((ty ^ s4) & 15)*4;
            const int mb = ((tx ^ s4) & 15)*4;
            #pragma unroll
            for (int j = 0; j < 4; j++) {
                const int s = s4*4 + j;
                float4 a4 = *(const float4*)&sAt[s*64 + ma];
                float4 b4 = *(const float4*)&sBt[s*64 + mb];
                float ra[4] = {a4.x, a4.y, a4.z, a4.w};
                float rb[4] = {b4.x, b4.y, b4.z, b4.w};
                #pragma unroll
                for (int r = 0; r < 4; r++)
                    #pragma unroll
                    for (int c = 0; c < 4; c++)
                        acc[r][c] = fmaf(ra[r], rb[c], acc[r][c]);
            }
        }
    }

    #pragma unroll
    for (int r = 0; r < 4; r++)
        #pragma unroll
        for (int c = 0; c < 4; c++)
            out[(size_t)(m0 + ty*4 + r)*EDIM + n0 + tx*4 + c] =
                acc[r][c] + bo[n0 + tx*4 + c];
}

// ---------------- launch ----------------
extern "C" void kernel_launch(void* const* d_in, const int* in_sizes, int n_in,
                              void* d_out, int out_size) {
    int idx_x = -1, idx_Er = -1, idx_Wo = -1, idx_bo = -1;
    int cand[8]; int ncand = 0;
    for (int scale = 1; scale <= 4; scale *= 4) {
        idx_x = idx_Er = idx_Wo = idx_bo = -1; ncand = 0;
        for (int i = 0; i < n_in; i++) {
            long long s = in_sizes[i];
            if      (s == (long long)BATCH*TLEN*EDIM*scale)   idx_x  = i;
            else if (s == (long long)HEADS_N*TLEN*SDIM*scale) idx_Er = i;
            else if (s == (long long)EDIM*EDIM*scale)         idx_Wo = i;
            else if (s == (long long)EDIM*scale)              idx_bo = i;
            else if (s == (long long)SDIM*SDIM*scale && ncand < 8) cand[ncand++] = i;
        }
        if (idx_x >= 0 && idx_Er >= 0 && idx_Wo >= 0 && idx_bo >= 0 && ncand == 4)
            break;
    }
    if (!(idx_x >= 0 && idx_Er >= 0 && idx_Wo >= 0 && idx_bo >= 0 && ncand == 4)) {
        int wi = (n_in >= 9) ? 3 : 2;
        idx_x = 0; cand[0] = 1; cand[1] = wi; cand[2] = wi + 1; cand[3] = wi + 2;
        idx_Er = wi + 3; idx_Wo = wi + 4; idx_bo = wi + 5; ncand = 4;
    }

    const float* x  = (const float*)d_in[idx_x];
    const float* Er = (const float*)d_in[idx_Er];
    const float* Wo = (const float*)d_in[idx_Wo];
    const float* bo = (const float*)d_in[idx_bo];
    float* out = (float*)d_out;

    const int PROJ_SMEM = (192*64 + 128*64) * (int)sizeof(float);   // 81920 B
    const int ATTN_SMEM = (4*4096) * (int)sizeof(float);            // 65536 B
    const int RG_SMEM   = (4*64*68) * (int)sizeof(float);           // 69632 B
    cudaFuncSetAttribute(proj_kernel, cudaFuncAttributeMaxDynamicSharedMemorySize, PROJ_SMEM);
    cudaFuncSetAttribute(attn_kernel, cudaFuncAttributeMaxDynamicSharedMemorySize, ATTN_SMEM);
    cudaFuncSetAttribute(relgemm_kernel, cudaFuncAttributeMaxDynamicSharedMemorySize, RG_SMEM);

    select_inputs<<<1, 256>>>((const float*)d_in[cand[0]], (const float*)d_in[cand[1]],
                              (const float*)d_in[cand[2]], (const float*)d_in[cand[3]],
                              (idx_x == 0) ? 1 : 0);
    proj_kernel<<<dim3(TLEN/128, HEADS_N, BATCH), 256, PROJ_SMEM>>>(x);
    relgemm_kernel<<<dim3(528, HEADS_N, BATCH), 256, RG_SMEM>>>(Er);
    vmean_kernel<<<BATCH*HEADS_N, 256>>>();
    attn_kernel<<<dim3(TLEN/64, HEADS_N, BATCH), 256, ATTN_SMEM>>>();
    outproj_kernel<<<dim3((BATCH*TLEN)/64, EDIM/64), 256>>>(Wo, bo, out);
}

// round 9
// speedup vs baseline: 1.0986x; 1.0791x over previous
#include <cuda_runtime.h>
#include <math.h>

#define TLEN    2048
#define HEADS_N 8
#define BATCH   2
#define SDIM    64
#define EDIM    512
#define QE_BH   2162688   // 4096 * 528 floats per (b,h)

// ---------------- scratch + resolved input pointers (device-resident) ----------
__device__ float g_q[BATCH*HEADS_N*TLEN*SDIM];
__device__ float g_k[BATCH*HEADS_N*TLEN*SDIM];
__device__ float g_v[BATCH*HEADS_N*TLEN*SDIM];
__device__ float g_vmean[BATCH*HEADS_N*SDIM];
__device__ float g_vpart[8][BATCH*HEADS_N][SDIM];
__device__ float g_attn[BATCH*TLEN*EDIM];
__device__ float g_qe[BATCH*HEADS_N*QE_BH];   // triangular-packed QE bands

__device__ const float*        g_pWq;
__device__ const float*        g_pWk;
__device__ const float*        g_pWv;
__device__ const unsigned int* g_pmask;

// ---------------- tf32 helpers ----------------
__device__ __forceinline__ unsigned int f2tf32(float x) {
    unsigned int r;
    asm("cvt.rna.tf32.f32 %0, %1;" : "=r"(r) : "f"(x));
    return r;
}
__device__ __forceinline__ void mma_tf32(float d[4],
        unsigned int a0, unsigned int a1, unsigned int a2, unsigned int a3,
        unsigned int b0, unsigned int b1) {
    asm("mma.sync.aligned.m16n8k8.row.col.f32.tf32.tf32.f32 "
        "{%0,%1,%2,%3}, {%4,%5,%6,%7}, {%8,%9}, {%0,%1,%2,%3};"
        : "+f"(d[0]), "+f"(d[1]), "+f"(d[2]), "+f"(d[3])
        : "r"(a0), "r"(a1), "r"(a2), "r"(a3), "r"(b0), "r"(b1));
}

// ---------------- prologue: content-based identification of mask ---------------
__global__ void select_inputs(const float* c0, const float* c1,
                              const float* c2, const float* c3, int x_first) {
    __shared__ int bad[4];
    const float* cand[4] = {c0, c1, c2, c3};
    if (threadIdx.x < 4) bad[threadIdx.x] = 0;
    __syncthreads();
    for (int j = 0; j < 4; j++) {
        const unsigned int* p = (const unsigned int*)cand[j];
        int b = 0;
        for (int i = threadIdx.x; i < SDIM*SDIM; i += blockDim.x) {
            unsigned int v = p[i];
            if (v != 0u && v != 1u && v != 0x3F800000u) { b = 1; break; }
        }
        if (b) atomicOr(&bad[j], 1);
    }
    __syncthreads();
    if (threadIdx.x == 0) {
        int mi = -1;
        for (int j = 0; j < 4; j++) if (!bad[j]) { mi = j; break; }
        if (mi < 0) mi = x_first ? 0 : 3;
        const float* rest[3]; int n = 0;
        for (int j = 0; j < 4; j++) if (j != mi) rest[n++] = cand[j];
        g_pmask = (const unsigned int*)cand[mi];
        if (x_first) { g_pWq = rest[0]; g_pWk = rest[1]; g_pWv = rest[2]; }
        else         { g_pWk = rest[0]; g_pWq = rest[1]; g_pWv = rest[2]; }
    }
}

// ---------------- QKV projection (swizzled float4 smem) ----------------
__global__ void proj_kernel(const float* __restrict__ x) {
    extern __shared__ float sm[];
    float* sW = sm;              // 192 rows x 64, swizzled
    float* sX = sm + 192*64;     // 128 rows x 64, swizzled
    const int t0 = blockIdx.x * 128;
    const int h  = blockIdx.y;
    const int b  = blockIdx.z;
    const int tid = threadIdx.x;
    const float* W[3] = {g_pWq, g_pWk, g_pWv};

    for (int k = tid; k < 3*64*16; k += 256) {
        int row = k >> 4, i4 = k & 15;
        int mm = row >> 6, o = row & 63;
        float4 f = *(const float4*)&W[mm][o*SDIM + i4*4];
        *(float4*)&sW[row*64 + ((i4 ^ o) & 15)*4] = f;
    }
    for (int k = tid; k < 128*16; k += 256) {
        int row = k >> 4, i4 = k & 15;
        float4 f = *(const float4*)&x[(size_t)(b*TLEN + t0 + row)*EDIM + h*SDIM + i4*4];
        *(float4*)&sX[row*64 + ((i4 ^ (row & 15)) & 15)*4] = f;
    }
    __syncthreads();

    for (int idx = tid; idx < 128*192; idx += 256) {
        int row = idx / 192;
        int rem = idx - row*192;
        float a = 0.f;
        const int mw = rem & 15;
        const int mx = row & 15;
        #pragma unroll
        for (int i4 = 0; i4 < 16; i4++) {
            float4 w4 = *(const float4*)&sW[rem*64 + ((i4 ^ mw) & 15)*4];
            float4 x4 = *(const float4*)&sX[row*64 + ((i4 ^ mx) & 15)*4];
            a = fmaf(w4.x, x4.x, a); a = fmaf(w4.y, x4.y, a);
            a = fmaf(w4.z, x4.z, a); a = fmaf(w4.w, x4.w, a);
        }
        int mm = rem >> 6, o = rem & 63;
        float* dst = (mm == 0) ? g_q : (mm == 1) ? g_k : g_v;
        dst[((size_t)(b*HEADS_N + h)*TLEN + t0 + row)*SDIM + o] = a;
    }
}

// ---------------- rel-pos GEMM: QE[i_l][o] = q_{i0+i_l} . Er[h][T-64-i0+o] ------
__global__ void __launch_bounds__(256) relgemm_kernel(const float* __restrict__ Er) {
    extern __shared__ float sm[];
    float* Qh = sm;              // [m=64][k] stride 68
    float* Ql = Qh + 64*68;
    float* Eh = Ql + 64*68;      // [k=64][n=o] stride 68
    float* El = Eh + 64*68;

    const int x = blockIdx.x;
    const int h = blockIdx.y, b = blockIdx.z;
    int it = (int)((sqrtf(8.f*(float)x + 1.f) - 1.f) * 0.5f);
    while ((it + 1)*(it + 2)/2 <= x) it++;
    while (it*(it + 1)/2 > x) it--;
    const int oc = x - it*(it + 1)/2;          // 0..it
    const int i0 = it * 64;
    const int j0 = TLEN - 64 - i0 + oc*64;     // Er row base (>= 0)

    const int tid = threadIdx.x;
    const float* gq = g_q + (size_t)(b*HEADS_N + h)*TLEN*SDIM + (size_t)i0*SDIM;
    const float* ge = Er + (size_t)h*TLEN*SDIM;

    #pragma unroll
    for (int kk = 0; kk < 4; kk++) {
        int k = kk*256 + tid;
        int m = k >> 4, s4 = (k & 15)*4;
        float4 f = *(const float4*)&gq[m*SDIM + s4];
        float hx = __uint_as_float(f2tf32(f.x));
        float hy = __uint_as_float(f2tf32(f.y));
        float hz = __uint_as_float(f2tf32(f.z));
        float hw = __uint_as_float(f2tf32(f.w));
        *(float4*)&Qh[m*68 + s4] = make_float4(hx, hy, hz, hw);
        *(float4*)&Ql[m*68 + s4] = make_float4(
            __uint_as_float(f2tf32(f.x - hx)), __uint_as_float(f2tf32(f.y - hy)),
            __uint_as_float(f2tf32(f.z - hz)), __uint_as_float(f2tf32(f.w - hw)));
    }
    #pragma unroll
    for (int kk = 0; kk < 4; kk++) {
        int k = kk*256 + tid;
        int s4 = (k >> 6)*4, o = k & 63;
        float4 f = *(const float4*)&ge[(size_t)(j0 + o)*SDIM + s4];
        float hv[4], lv[4];
        float fv[4] = {f.x, f.y, f.z, f.w};
        #pragma unroll
        for (int i = 0; i < 4; i++) {
            hv[i] = __uint_as_float(f2tf32(fv[i]));
            lv[i] = __uint_as_float(f2tf32(fv[i] - hv[i]));
        }
        #pragma unroll
        for (int i = 0; i < 4; i++) {
            Eh[(s4 + i)*68 + o] = hv[i];
            El[(s4 + i)*68 + o] = lv[i];
        }
    }
    __syncthreads();

    const int w = tid >> 5, lane = tid & 31;
    const int g = lane >> 2, tg = lane & 3;
    const int mr = (w & 3)*16 + g;
    const int nb = (w >> 2)*32;

    float d[4][4];
    #pragma unroll
    for (int nt = 0; nt < 4; nt++)
        #pragma unroll
        for (int i = 0; i < 4; i++) d[nt][i] = 0.f;

    #pragma unroll
    for (int kk = 0; kk < 8; kk++) {
        const int k0 = kk*8;
        unsigned int ah0 = __float_as_uint(Qh[mr*68 + k0 + tg]);
        unsigned int ah1 = __float_as_uint(Qh[(mr + 8)*68 + k0 + tg]);
        unsigned int ah2 = __float_as_uint(Qh[mr*68 + k0 + tg + 4]);
        unsigned int ah3 = __float_as_uint(Qh[(mr + 8)*68 + k0 + tg + 4]);
        unsigned int al0 = __float_as_uint(Ql[mr*68 + k0 + tg]);
        unsigned int al1 = __float_as_uint(Ql[(mr + 8)*68 + k0 + tg]);
        unsigned int al2 = __float_as_uint(Ql[mr*68 + k0 + tg + 4]);
        unsigned int al3 = __float_as_uint(Ql[(mr + 8)*68 + k0 + tg + 4]);
        #pragma unroll
        for (int nt = 0; nt < 4; nt++) {
            const int n = nb + nt*8 + g;
            unsigned int bh0 = __float_as_uint(Eh[(k0 + tg)*68 + n]);
            unsigned int bh1 = __float_as_uint(Eh[(k0 + tg + 4)*68 + n]);
            unsigned int bl0 = __float_as_uint(El[(k0 + tg)*68 + n]);
            unsigned int bl1 = __float_as_uint(El[(k0 + tg + 4)*68 + n]);
            mma_tf32(d[nt], ah0, ah1, ah2, ah3, bh0, bh1);
            mma_tf32(d[nt], ah0, ah1, ah2, ah3, bl0, bl1);
            mma_tf32(d[nt], al0, al1, al2, al3, bh0, bh1);
        }
    }

    const int W = 64*(it + 1);
    float* qb = g_qe + (size_t)(b*HEADS_N + h)*QE_BH + (size_t)4096*(it*(it + 1)/2);
    const int colb = oc*64 + nb;
    #pragma unroll
    for (int nt = 0; nt < 4; nt++) {
        const int col = colb + nt*8 + 2*tg;
        *(float2*)&qb[(size_t)mr*W + col]       = make_float2(d[nt][0], d[nt][1]);
        *(float2*)&qb[(size_t)(mr + 8)*W + col] = make_float2(d[nt][2], d[nt][3]);
    }
}

// ---------------- V mean, two-stage (deterministic, full-chip) ----------------
__global__ void vmean1_kernel() {
    const int bh = blockIdx.x, ch = blockIdx.y;
    const int tid = threadIdx.x;
    const int d = tid & 63, sub = tid >> 6;
    __shared__ float red[4][64];
    float a = 0.f;
    for (int l = ch*256 + sub; l < (ch + 1)*256; l += 4)
        a += g_v[((size_t)bh*TLEN + l)*SDIM + d];
    red[sub][d] = a;
    __syncthreads();
    if (sub == 0)
        g_vpart[ch][bh][d] = red[0][d] + red[1][d] + red[2][d] + red[3][d];
}
__global__ void vmean2_kernel() {
    const int bh = blockIdx.x, d = threadIdx.x;
    float a = 0.f;
    #pragma unroll
    for (int c = 0; c < 8; c++) a += g_vpart[c][bh][d];
    g_vmean[bh*SDIM + d] = a * (1.f/(float)TLEN);
}

// ---------------- tensor-core flash attention (QK + QE band + PV) --------------
// grid: (TLEN/64 reversed, H, B), 128 threads = 4 warps; warp w owns S rows
// [w*16, w*16+16). 3x tf32 split everywhere (fp32-grade).
#define AST 72   // smem row stride (words)
__global__ void __launch_bounds__(128, 3) attn_kernel() {
    extern __shared__ float sm[];
    float* sQ = sm;              // [i][s]  64 x AST
    float* sK = sQ + 64*AST;     // [c][s]  64 x AST (pre-scaled by 512^-0.5)
    float* sV = sK + 64*AST;     // [lc][d] 64 x AST
    float* sP = sV + 64*AST;     // [i][lc] 64 x AST

    const int rbx = (int)gridDim.x - 1 - (int)blockIdx.x;   // heavy tiles first
    const int i0 = rbx * 64;
    const int h  = blockIdx.y;
    const int b  = blockIdx.z;
    const int tid = threadIdx.x;
    const int w = tid >> 5, lane = tid & 31;
    const int g = lane >> 2, tg = lane & 3;
    const int rA = w*16 + g, rB = rA + 8;
    const float scale2 = 0.04419417382415922f;   // 512^-0.5

    const size_t bh = (size_t)(b*HEADS_N + h);
    const float* gq = g_q + bh*TLEN*SDIM;
    const float* gk = g_k + bh*TLEN*SDIM;
    const float* gv = g_v + bh*TLEN*SDIM;

    const int it = i0 >> 6;
    const int Wqe = 64*(it + 1);
    const float* qeb = g_qe + bh*QE_BH + (size_t)4096*(it*(it + 1)/2);
    const int omax = i0 + 63;

    // stage Q once
    for (int k = tid; k < 1024; k += 128) {
        int li = k >> 4, s4 = (k & 15)*4;
        *(float4*)&sQ[li*AST + s4] =
            *(const float4*)&gq[(size_t)(i0 + li)*SDIM + s4];
    }

    float mA = -1e30f, mB = -1e30f, lA = 0.f, lB = 0.f;
    float O[8][4];
    #pragma unroll
    for (int nt = 0; nt < 8; nt++)
        #pragma unroll
        for (int i = 0; i < 4; i++) O[nt][i] = 0.f;

    for (int ct = 0; ct <= it; ct++) {
        const int c0 = ct * 64;
        __syncthreads();
        for (int k = tid; k < 1024; k += 128) {
            int li = k >> 4, s4 = (k & 15)*4;
            float4 f = *(const float4*)&gk[(size_t)(c0 + li)*SDIM + s4];
            f.x *= scale2; f.y *= scale2; f.z *= scale2; f.w *= scale2;
            *(float4*)&sK[li*AST + s4] = f;
            *(float4*)&sV[li*AST + s4] =
                *(const float4*)&gv[(size_t)(c0 + li)*SDIM + s4];
        }
        __syncthreads();

        // ---- S = Q K^T (3x tf32) ----
        float acc[8][4];
        #pragma unroll
        for (int nt = 0; nt < 8; nt++)
            #pragma unroll
            for (int i = 0; i < 4; i++) acc[nt][i] = 0.f;

        #pragma unroll
        for (int kk = 0; kk < 8; kk++) {
            const int k0 = kk*8;
            float q0 = sQ[rA*AST + k0 + tg];
            float q1 = sQ[rB*AST + k0 + tg];
            float q2 = sQ[rA*AST + k0 + tg + 4];
            float q3 = sQ[rB*AST + k0 + tg + 4];
            unsigned int ah0 = f2tf32(q0), ah1 = f2tf32(q1);
            unsigned int ah2 = f2tf32(q2), ah3 = f2tf32(q3);
            unsigned int al0 = f2tf32(q0 - __uint_as_float(ah0));
            unsigned int al1 = f2tf32(q1 - __uint_as_float(ah1));
            unsigned int al2 = f2tf32(q2 - __uint_as_float(ah2));
            unsigned int al3 = f2tf32(q3 - __uint_as_float(ah3));
            #pragma unroll
            for (int nt = 0; nt < 8; nt++) {
                const int n = nt*8 + g;
                float b0f = sK[n*AST + k0 + tg];
                float b1f = sK[n*AST + k0 + tg + 4];
                unsigned int bh0 = f2tf32(b0f), bh1 = f2tf32(b1f);
                unsigned int bl0 = f2tf32(b0f - __uint_as_float(bh0));
                unsigned int bl1 = f2tf32(b1f - __uint_as_float(bh1));
                mma_tf32(acc[nt], ah0, ah1, ah2, ah3, bh0, bh1);
                mma_tf32(acc[nt], ah0, ah1, ah2, ah3, bl0, bl1);
                mma_tf32(acc[nt], al0, al1, al2, al3, bh0, bh1);
            }
        }

        // ---- add precomputed rel-pos band + causal mask ----
        #pragma unroll
        for (int nt = 0; nt < 8; nt++) {
            const int cl = nt*8 + 2*tg;
            const int oA = 63 - rA + c0 + cl;
            const int oB = 63 - rB + c0 + cl;
            if (oA     <= omax) acc[nt][0] += __ldg(qeb + (size_t)rA*Wqe + oA);
            if (oA + 1 <= omax) acc[nt][1] += __ldg(qeb + (size_t)rA*Wqe + oA + 1);
            if (oB     <= omax) acc[nt][2] += __ldg(qeb + (size_t)rB*Wqe + oB);
            if (oB + 1 <= omax) acc[nt][3] += __ldg(qeb + (size_t)rB*Wqe + oB + 1);
            if (ct == it) {
                if (cl     > rA) acc[nt][0] = -1e30f;
                if (cl + 1 > rA) acc[nt][1] = -1e30f;
                if (cl     > rB) acc[nt][2] = -1e30f;
                if (cl + 1 > rB) acc[nt][3] = -1e30f;
            }
        }

        // ---- online softmax (rows rA, rB; quad = lanes sharing g) ----
        float mxA = -1e30f, mxB = -1e30f;
        #pragma unroll
        for (int nt = 0; nt < 8; nt++) {
            mxA = fmaxf(mxA, fmaxf(acc[nt][0], acc[nt][1]));
            mxB = fmaxf(mxB, fmaxf(acc[nt][2], acc[nt][3]));
        }
        mxA = fmaxf(mxA, __shfl_xor_sync(0xffffffffu, mxA, 1));
        mxA = fmaxf(mxA, __shfl_xor_sync(0xffffffffu, mxA, 2));
        mxB = fmaxf(mxB, __shfl_xor_sync(0xffffffffu, mxB, 1));
        mxB = fmaxf(mxB, __shfl_xor_sync(0xffffffffu, mxB, 2));
        const float mnA = fmaxf(mA, mxA), mnB = fmaxf(mB, mxB);
        const float cA = __expf(mA - mnA), cB = __expf(mB - mnB);
        float sA = 0.f, sB = 0.f;
        #pragma unroll
        for (int nt = 0; nt < 8; nt++) {
            acc[nt][0] = __expf(acc[nt][0] - mnA);
            acc[nt][1] = __expf(acc[nt][1] - mnA);
            acc[nt][2] = __expf(acc[nt][2] - mnB);
            acc[nt][3] = __expf(acc[nt][3] - mnB);
            sA += acc[nt][0] + acc[nt][1];
            sB += acc[nt][2] + acc[nt][3];
        }
        sA += __shfl_xor_sync(0xffffffffu, sA, 1);
        sA += __shfl_xor_sync(0xffffffffu, sA, 2);
        sB += __shfl_xor_sync(0xffffffffu, sB, 1);
        sB += __shfl_xor_sync(0xffffffffu, sB, 2);
        lA = lA*cA + sA;  mA = mnA;
        lB = lB*cB + sB;  mB = mnB;
        #pragma unroll
        for (int nt = 0; nt < 8; nt++) {
            O[nt][0] *= cA; O[nt][1] *= cA;
            O[nt][2] *= cB; O[nt][3] *= cB;
        }

        // ---- re-layout P via warp-private smem (c-frag -> a-frag) ----
        #pragma unroll
        for (int nt = 0; nt < 8; nt++) {
            *(float2*)&sP[rA*AST + nt*8 + 2*tg] = make_float2(acc[nt][0], acc[nt][1]);
            *(float2*)&sP[rB*AST + nt*8 + 2*tg] = make_float2(acc[nt][2], acc[nt][3]);
        }
        __syncwarp();

        // ---- O += P V (3x tf32) ----
        #pragma unroll
        for (int kk = 0; kk < 8; kk++) {
            const int k0 = kk*8;
            float p0 = sP[rA*AST + k0 + tg];
            float p1 = sP[rB*AST + k0 + tg];
            float p2 = sP[rA*AST + k0 + tg + 4];
            float p3 = sP[rB*AST + k0 + tg + 4];
            unsigned int ah0 = f2tf32(p0), ah1 = f2tf32(p1);
            unsigned int ah2 = f2tf32(p2), ah3 = f2tf32(p3);
            unsigned int al0 = f2tf32(p0 - __uint_as_float(ah0));
            unsigned int al1 = f2tf32(p1 - __uint_as_float(ah1));
            unsigned int al2 = f2tf32(p2 - __uint_as_float(ah2));
            unsigned int al3 = f2tf32(p3 - __uint_as_float(ah3));
            #pragma unroll
            for (int nt = 0; nt < 8; nt++) {
                const int n = nt*8 + g;
                float b0f = sV[(k0 + tg)*AST + n];
                float b1f = sV[(k0 + tg + 4)*AST + n];
                unsigned int bh0 = f2tf32(b0f), bh1 = f2tf32(b1f);
                unsigned int bl0 = f2tf32(b0f - __uint_as_float(bh0));
                unsigned int bl1 = f2tf32(b1f - __uint_as_float(bh1));
                mma_tf32(O[nt], ah0, ah1, ah2, ah3, bh0, bh1);
                mma_tf32(O[nt], ah0, ah1, ah2, ah3, bl0, bl1);
                mma_tf32(O[nt], al0, al1, al2, al3, bh0, bh1);
            }
        }
    }

    // ---- epilogue: scrambled layout R = h*256 + (i>>3), C = (i&7)*64 + d ----
    const int iA = i0 + rA, iB = i0 + rB;
    const unsigned int mkA = g_pmask[b*TLEN + iA];
    const unsigned int mkB = g_pmask[b*TLEN + iB];
    const float invA = 1.f / lA, invB = 1.f / lB;
    const size_t rowA = ((size_t)(b*TLEN) + h*256 + (iA >> 3))*EDIM + ((iA & 7) << 6);
    const size_t rowB = ((size_t)(b*TLEN) + h*256 + (iB >> 3))*EDIM + ((iB & 7) << 6);
    #pragma unroll
    for (int nt = 0; nt < 8; nt++) {
        const int d0 = nt*8 + 2*tg;
        float2 vm = *(const float2*)&g_vmean[(b*HEADS_N + h)*SDIM + d0];
        float2 oa = (mkA != 0u) ? make_float2(O[nt][0]*invA, O[nt][1]*invA) : vm;
        float2 ob = (mkB != 0u) ? make_float2(O[nt][2]*invB, O[nt][3]*invB) : vm;
        *(float2*)&g_attn[rowA + d0] = oa;
        *(float2*)&g_attn[rowB + d0] = ob;
    }
}

// ---------------- output projection: out = attnS @ Wo^T + bo -------------------
__global__ void outproj_kernel(const float* __restrict__ Wo,
                               const float* __restrict__ bo,
                               float* __restrict__ out) {
    __shared__ float sAt[64*64];
    __shared__ float sBt[64*64];
    const int m0 = blockIdx.x * 64;
    const int n0 = blockIdx.y * 64;
    const int tid = threadIdx.x;
    const int tx = tid & 15;
    const int ty = tid >> 4;

    float acc[4][4];
    #pragma unroll
    for (int r = 0; r < 4; r++)
        #pragma unroll
        for (int c = 0; c < 4; c++) acc[r][c] = 0.f;

    for (int kc = 0; kc < EDIM; kc += 64) {
        __syncthreads();
        for (int k = tid; k < 1024; k += 256) {
            int rr = k >> 4, c4 = k & 15;
            float4 a = *(const float4*)&g_attn[(size_t)(m0 + rr)*EDIM + kc + c4*4];
            int basea = c4*4*64 + (((rr >> 2) ^ c4) & 15)*4 + (rr & 3);
            sAt[basea]       = a.x;
            sAt[basea + 64]  = a.y;
            sAt[basea + 128] = a.z;
            sAt[basea + 192] = a.w;
            float4 bw = *(const float4*)&Wo[(size_t)(n0 + rr)*EDIM + kc + c4*4];
            sBt[basea]       = bw.x;
            sBt[basea + 64]  = bw.y;
            sBt[basea + 128] = bw.z;
            sBt[basea + 192] = bw.w;
        }
        __syncthreads();
        #pragma unroll 4
        for (int s4 = 0; s4 < 16; s4++) {
            const int ma = ((ty ^ s4) & 15)*4;
            const int mb = ((tx ^ s4) & 15)*4;
            #pragma unroll
            for (int j = 0; j < 4; j++) {
                const int s = s4*4 + j;
                float4 a4 = *(const float4*)&sAt[s*64 + ma];
                float4 b4 = *(const float4*)&sBt[s*64 + mb];
                float ra[4] = {a4.x, a4.y, a4.z, a4.w};
                float rb[4] = {b4.x, b4.y, b4.z, b4.w};
                #pragma unroll
                for (int r = 0; r < 4; r++)
                    #pragma unroll
                    for (int c = 0; c < 4; c++)
                        acc[r][c] = fmaf(ra[r], rb[c], acc[r][c]);
            }
        }
    }

    #pragma unroll
    for (int r = 0; r < 4; r++)
        #pragma unroll
        for (int c = 0; c < 4; c++)
            out[(size_t)(m0 + ty*4 + r)*EDIM + n0 + tx*4 + c] =
                acc[r][c] + bo[n0 + tx*4 + c];
}

// ---------------- launch ----------------
extern "C" void kernel_launch(void* const* d_in, const int* in_sizes, int n_in,
                              void* d_out, int out_size) {
    int idx_x = -1, idx_Er = -1, idx_Wo = -1, idx_bo = -1;
    int cand[8]; int ncand = 0;
    for (int scale = 1; scale <= 4; scale *= 4) {
        idx_x = idx_Er = idx_Wo = idx_bo = -1; ncand = 0;
        for (int i = 0; i < n_in; i++) {
            long long s = in_sizes[i];
            if      (s == (long long)BATCH*TLEN*EDIM*scale)   idx_x  = i;
            else if (s == (long long)HEADS_N*TLEN*SDIM*scale) idx_Er = i;
            else if (s == (long long)EDIM*EDIM*scale)         idx_Wo = i;
            else if (s == (long long)EDIM*scale)              idx_bo = i;
            else if (s == (long long)SDIM*SDIM*scale && ncand < 8) cand[ncand++] = i;
        }
        if (idx_x >= 0 && idx_Er >= 0 && idx_Wo >= 0 && idx_bo >= 0 && ncand == 4)
            break;
    }
    if (!(idx_x >= 0 && idx_Er >= 0 && idx_Wo >= 0 && idx_bo >= 0 && ncand == 4)) {
        int wi = (n_in >= 9) ? 3 : 2;
        idx_x = 0; cand[0] = 1; cand[1] = wi; cand[2] = wi + 1; cand[3] = wi + 2;
        idx_Er = wi + 3; idx_Wo = wi + 4; idx_bo = wi + 5; ncand = 4;
    }

    const float* x  = (const float*)d_in[idx_x];
    const float* Er = (const float*)d_in[idx_Er];
    const float* Wo = (const float*)d_in[idx_Wo];
    const float* bo = (const float*)d_in[idx_bo];
    float* out = (float*)d_out;

    const int PROJ_SMEM = (192*64 + 128*64) * (int)sizeof(float);   // 81920 B
    const int ATTN_SMEM = (4*64*AST) * (int)sizeof(float);          // 73728 B
    const int RG_SMEM   = (4*64*68) * (int)sizeof(float);           // 69632 B
    cudaFuncSetAttribute(proj_kernel, cudaFuncAttributeMaxDynamicSharedMemorySize, PROJ_SMEM);
    cudaFuncSetAttribute(attn_kernel, cudaFuncAttributeMaxDynamicSharedMemorySize, ATTN_SMEM);
    cudaFuncSetAttribute(relgemm_kernel, cudaFuncAttributeMaxDynamicSharedMemorySize, RG_SMEM);

    select_inputs<<<1, 256>>>((const float*)d_in[cand[0]], (const float*)d_in[cand[1]],
                              (const float*)d_in[cand[2]], (const float*)d_in[cand[3]],
                              (idx_x == 0) ? 1 : 0);
    proj_kernel<<<dim3(TLEN/128, HEADS_N, BATCH), 256, PROJ_SMEM>>>(x);
    relgemm_kernel<<<dim3(528, HEADS_N, BATCH), 256, RG_SMEM>>>(Er);
    vmean1_kernel<<<dim3(BATCH*HEADS_N, 8), 256>>>();
    vmean2_kernel<<<BATCH*HEADS_N, SDIM>>>();
    attn_kernel<<<dim3(TLEN/64, HEADS_N, BATCH), 128, ATTN_SMEM>>>();
    outproj_kernel<<<dim3((BATCH*TLEN)/64, EDIM/64), 256>>>(Wo, bo, out);
}